// round 1
// baseline (speedup 1.0000x reference)
#include <cuda_runtime.h>
#include <cuda_bf16.h>
#include <cstdint>

#define B_SZ     2
#define N_IN     50000
#define N_OUT    12500
#define NNZ      500000
#define IN_C     256
#define OUT_C    256
#define M_ROWS   (B_SZ * N_OUT)   // 25000

// ---------------- scratch (device globals; no allocation allowed) ------------
__device__ int   g_counts[N_OUT];
__device__ int   g_offsets[N_OUT + 1];
__device__ int   g_cursor[N_OUT];
__device__ int   g_scol[NNZ];
__device__ float g_sval[NNZ];
__device__ float g_ax[(size_t)M_ROWS * IN_C];   // 25.6 MB

// ---------------- CSR build --------------------------------------------------
__global__ void k_zero_counts() {
    int i = blockIdx.x * blockDim.x + threadIdx.x;
    if (i < N_OUT) g_counts[i] = 0;
}

__global__ void k_hist(const int* __restrict__ rows) {
    int e = blockIdx.x * blockDim.x + threadIdx.x;
    if (e < NNZ) atomicAdd(&g_counts[rows[e]], 1);
}

// single block, 1024 threads, 13 values each (13*1024 >= 12500)
__global__ void k_scan() {
    __shared__ int s[1024];
    const int VT = 13;
    int t = threadIdx.x;
    int base = t * VT;
    int loc[VT];
    int sum = 0;
#pragma unroll
    for (int i = 0; i < VT; i++) {
        int idx = base + i;
        int v = (idx < N_OUT) ? g_counts[idx] : 0;
        loc[i] = v;
        sum += v;
    }
    s[t] = sum;
    __syncthreads();
    // Hillis-Steele inclusive scan over 1024 partials
    for (int off = 1; off < 1024; off <<= 1) {
        int v = s[t];
        if (t >= off) v += s[t - off];
        __syncthreads();
        s[t] = v;
        __syncthreads();
    }
    int run = (t == 0) ? 0 : s[t - 1];   // exclusive prefix for this thread
#pragma unroll
    for (int i = 0; i < VT; i++) {
        int idx = base + i;
        if (idx < N_OUT) {
            g_offsets[idx] = run;
            g_cursor[idx]  = run;
        }
        run += loc[i];
    }
    if (t == 1023) g_offsets[N_OUT] = s[1023];
}

__global__ void k_fill(const int* __restrict__ rows,
                       const int* __restrict__ cols,
                       const float* __restrict__ vals) {
    int e = blockIdx.x * blockDim.x + threadIdx.x;
    if (e < NNZ) {
        int r = rows[e];
        int p = atomicAdd(&g_cursor[r], 1);
        g_scol[p] = cols[e];
        g_sval[p] = vals[e];
    }
}

// ---------------- SpMM: one block per (row, batch), 256 ch threads ----------
__global__ __launch_bounds__(IN_C) void k_spmm(const float* __restrict__ x) {
    int row = blockIdx.x;
    int b   = blockIdx.y;
    int t   = threadIdx.x;

    int s = g_offsets[row];
    int e = g_offsets[row + 1];
    const float* __restrict__ xb = x + (size_t)b * N_IN * IN_C;

    float acc0 = 0.f, acc1 = 0.f;
    int j = s;
    for (; j + 4 <= e; j += 4) {
        int   c0 = g_scol[j + 0], c1 = g_scol[j + 1];
        int   c2 = g_scol[j + 2], c3 = g_scol[j + 3];
        float v0 = g_sval[j + 0], v1 = g_sval[j + 1];
        float v2 = g_sval[j + 2], v3 = g_sval[j + 3];
        float x0 = __ldg(xb + (size_t)c0 * IN_C + t);
        float x1 = __ldg(xb + (size_t)c1 * IN_C + t);
        float x2 = __ldg(xb + (size_t)c2 * IN_C + t);
        float x3 = __ldg(xb + (size_t)c3 * IN_C + t);
        acc0 = fmaf(v0, x0, acc0);
        acc1 = fmaf(v1, x1, acc1);
        acc0 = fmaf(v2, x2, acc0);
        acc1 = fmaf(v3, x3, acc1);
    }
    for (; j < e; j++) {
        int   c = g_scol[j];
        float v = g_sval[j];
        acc0 = fmaf(v, __ldg(xb + (size_t)c * IN_C + t), acc0);
    }
    g_ax[((size_t)b * N_OUT + row) * IN_C + t] = acc0 + acc1;
}

// ---------------- GEMM: C[M x 256] = AX @ W + bias(row % N_OUT) -------------
#define BM 64
#define BN 64
#define BK 16
#define TM 4
#define TN 4

__global__ __launch_bounds__(256) void k_gemm(const float* __restrict__ W,
                                              const float* __restrict__ bias,
                                              float* __restrict__ C) {
    __shared__ float sA[BK][BM + 4];
    __shared__ float sB[BK][BN];

    int tx = threadIdx.x;                 // 0..255
    int block_row = blockIdx.y * BM;
    int block_col = blockIdx.x * BN;

    int tcol = tx & 15;                   // 0..15
    int trow = tx >> 4;                   // 0..15

    // A-tile load mapping: 64 rows x 16 cols; each thread loads one float4
    int a_r = tx >> 2;
    int a_c = (tx & 3) * 4;
    // B-tile load mapping: 16 rows x 64 cols
    int b_r = tx >> 4;
    int b_c = (tx & 15) * 4;

    float acc[TM][TN];
#pragma unroll
    for (int i = 0; i < TM; i++)
#pragma unroll
        for (int j = 0; j < TN; j++) acc[i][j] = 0.f;

    for (int k0 = 0; k0 < IN_C; k0 += BK) {
        float4 av = make_float4(0.f, 0.f, 0.f, 0.f);
        int gr = block_row + a_r;
        if (gr < M_ROWS)
            av = *reinterpret_cast<const float4*>(&g_ax[(size_t)gr * IN_C + k0 + a_c]);
        sA[a_c + 0][a_r] = av.x;
        sA[a_c + 1][a_r] = av.y;
        sA[a_c + 2][a_r] = av.z;
        sA[a_c + 3][a_r] = av.w;

        float4 bv = *reinterpret_cast<const float4*>(W + (size_t)(k0 + b_r) * OUT_C + block_col + b_c);
        *reinterpret_cast<float4*>(&sB[b_r][b_c]) = bv;

        __syncthreads();

#pragma unroll
        for (int k = 0; k < BK; k++) {
            float ar[TM], br[TN];
#pragma unroll
            for (int i = 0; i < TM; i++) ar[i] = sA[k][trow * TM + i];
#pragma unroll
            for (int j = 0; j < TN; j++) br[j] = sB[k][tcol * TN + j];
#pragma unroll
            for (int i = 0; i < TM; i++)
#pragma unroll
                for (int j = 0; j < TN; j++)
                    acc[i][j] = fmaf(ar[i], br[j], acc[i][j]);
        }
        __syncthreads();
    }

#pragma unroll
    for (int i = 0; i < TM; i++) {
        int row = block_row + trow * TM + i;
        if (row >= M_ROWS) continue;
        int brow = (row >= N_OUT) ? (row - N_OUT) : row;
        int col = block_col + tcol * TN;
        float4 bb = *reinterpret_cast<const float4*>(bias + (size_t)brow * OUT_C + col);
        float4 out;
        out.x = acc[i][0] + bb.x;
        out.y = acc[i][1] + bb.y;
        out.z = acc[i][2] + bb.z;
        out.w = acc[i][3] + bb.w;
        *reinterpret_cast<float4*>(C + (size_t)row * OUT_C + col) = out;
    }
}

// ---------------- launch -----------------------------------------------------
extern "C" void kernel_launch(void* const* d_in, const int* in_sizes, int n_in,
                              void* d_out, int out_size) {
    const float* x      = (const float*)d_in[0];
    const int*   rows   = (const int*)d_in[1];
    const int*   cols   = (const int*)d_in[2];
    const float* vals   = (const float*)d_in[3];
    const float* weight = (const float*)d_in[4];
    const float* bias   = (const float*)d_in[5];
    float*       out    = (float*)d_out;

    k_zero_counts<<<(N_OUT + 255) / 256, 256>>>();
    k_hist<<<(NNZ + 255) / 256, 256>>>(rows);
    k_scan<<<1, 1024>>>();
    k_fill<<<(NNZ + 255) / 256, 256>>>(rows, cols, vals);

    dim3 sgrid(N_OUT, B_SZ);
    k_spmm<<<sgrid, IN_C>>>(x);

    dim3 ggrid(OUT_C / BN, (M_ROWS + BM - 1) / BM);
    k_gemm<<<ggrid, 256>>>(weight, bias, out);
}